// round 8
// baseline (speedup 1.0000x reference)
#include <cuda_runtime.h>
#include <cuda_bf16.h>
#include <cfloat>

// SpatialAttentionModule: x[16,64,256,256] f32
//   avg = mean_c(x), mx = max_c(x); mask = sigmoid(conv7x7_2to1([avg;mx]) + b)
//   out = x * mask
//
// K1 reduce:    channel mean/max -> g_avg/g_max (L2-resident). unroll 16 (44.4us measured).
// K2 conv_mask: 7x7 conv + sigmoid -> g_mask (4 MB, L2-resident). ~7us measured (R4).
// K3 scale:     EXACT R3 stream mapping (block=(b,h); tid=(csub,q); unroll-4 cg loop)
//               -- the best-measured stream (5.8 TB/s) -- minus the conv prologue.
//               R4's scale regression came from its linear mapping, not decoupling.

#define B_  16
#define C_  64
#define H_  256
#define W_  256
#define HW  (H_ * W_)
#define HW4 (HW / 4)               // float4 per (b,c) plane
#define KS  7
#define PADK 3
#define WPAD (W_ + 2 * PADK)       // 262

__device__ float g_avg[B_ * HW];
__device__ float g_max[B_ * HW];
__device__ float g_mask[B_ * HW];

__global__ __launch_bounds__(256) void reduce_kernel(const float4* __restrict__ x) {
    int g  = blockIdx.x * 256 + threadIdx.x;
    int b  = g >> 14;
    int hw = g & (HW4 - 1);

    const float4* p = x + ((size_t)b * C_) * HW4 + hw;

    float4 s = make_float4(0.f, 0.f, 0.f, 0.f);
    float4 m = make_float4(-FLT_MAX, -FLT_MAX, -FLT_MAX, -FLT_MAX);

    #pragma unroll 16
    for (int c = 0; c < C_; ++c) {
        float4 v = __ldcs(p + (size_t)c * HW4);
        s.x += v.x; s.y += v.y; s.z += v.z; s.w += v.w;
        m.x = fmaxf(m.x, v.x); m.y = fmaxf(m.y, v.y);
        m.z = fmaxf(m.z, v.z); m.w = fmaxf(m.w, v.w);
    }

    const float inv = 1.0f / (float)C_;
    float4 a = make_float4(s.x * inv, s.y * inv, s.z * inv, s.w * inv);
    reinterpret_cast<float4*>(g_avg)[g] = a;   // default policy: keep in L2
    reinterpret_cast<float4*>(g_max)[g] = m;
}

// One block per (b, h) row; 256 threads = 1 mask pixel each.
__global__ __launch_bounds__(256) void conv_mask_kernel(const float* __restrict__ conv_w,
                                                        const float* __restrict__ conv_b) {
    __shared__ float sw[2 * KS * KS];
    __shared__ float sm[2 * KS * WPAD];

    const int tid = threadIdx.x;
    const int b   = blockIdx.x >> 8;
    const int h   = blockIdx.x & (H_ - 1);

    if (tid < 2 * KS * KS) sw[tid] = __ldg(&conv_w[tid]);

    for (int i = tid; i < 2 * KS * WPAD; i += 256) {
        int ic = i / (KS * WPAD);
        int r  = i - ic * (KS * WPAD);
        int kh = r / WPAD;
        int wp = r - kh * WPAD;
        int wc = wp - PADK;
        int hh = h + kh - PADK;
        float v = 0.f;
        if (hh >= 0 && hh < H_ && wc >= 0 && wc < W_) {
            const float* plane = ic ? g_max : g_avg;
            v = __ldg(&plane[((size_t)b * H_ + hh) * W_ + wc]);   // L2 hit
        }
        sm[i] = v;
    }
    __syncthreads();

    float acc = __ldg(&conv_b[0]);
    #pragma unroll
    for (int ic = 0; ic < 2; ++ic) {
        #pragma unroll
        for (int kh = 0; kh < KS; ++kh) {
            const float* row = &sm[(ic * KS + kh) * WPAD + tid];
            const float* wr  = &sw[(ic * KS + kh) * KS];
            #pragma unroll
            for (int kw = 0; kw < KS; ++kw)
                acc += row[kw] * wr[kw];
        }
    }
    g_mask[((size_t)b * H_ + h) * W_ + tid] = 1.0f / (1.0f + __expf(-acc));
}

// Pure stream with the R3 mapping: block=(b,h), 256 threads = 4 ch x 64 q-columns.
__global__ __launch_bounds__(256) void scale_kernel(const float4* __restrict__ x4,
                                                    float4* __restrict__ o4) {
    const int tid  = threadIdx.x;
    const int b    = blockIdx.x >> 8;
    const int h    = blockIdx.x & (H_ - 1);
    const int q    = tid & 63;
    const int csub = tid >> 6;

    const float4 mk =
        __ldg(&reinterpret_cast<const float4*>(g_mask)[((size_t)b * H_ + h) * (W_ / 4) + q]);

    #pragma unroll 4
    for (int cg = 0; cg < C_ / 4; ++cg) {
        int c = cg * 4 + csub;
        size_t idx = (((size_t)b * C_ + c) * H_ + h) * (W_ / 4) + q;
        float4 v = __ldcs(&x4[idx]);
        v.x *= mk.x; v.y *= mk.y; v.z *= mk.z; v.w *= mk.w;
        __stcs(&o4[idx], v);
    }
}

extern "C" void kernel_launch(void* const* d_in, const int* in_sizes, int n_in,
                              void* d_out, int out_size) {
    const float* x      = (const float*)d_in[0];
    const float* conv_w = (const float*)d_in[1];
    const float* conv_b = (const float*)d_in[2];
    float* out          = (float*)d_out;

    reduce_kernel<<<(B_ * HW4) / 256, 256>>>((const float4*)x);
    conv_mask_kernel<<<B_ * H_, 256>>>(conv_w, conv_b);
    scale_kernel<<<B_ * H_, 256>>>((const float4*)x, (float4*)out);
}

// round 10
// speedup vs baseline: 1.1850x; 1.1850x over previous
#include <cuda_runtime.h>
#include <cuda_bf16.h>
#include <cfloat>

// SpatialAttentionModule: x[16,64,256,256] f32
//   avg = mean_c(x), mx = max_c(x); mask = sigmoid(conv7x7_2to1([avg;mx]) + b)
//   out = x * mask
//
// Recombination of measured-best components:
//  K1 reduce: unroll 16, __ldcs  -> 42.0us @ 81.9% DRAM (R8 measured)
//  K2 fuse:   exact R3 kernel (1-row blocks, SMEM mask, (csub,q) stream, 31 regs)
//             -> 94.2us @ 65.7% DRAM (R3 measured). All variants of this lost.

#define B_  16
#define C_  64
#define H_  256
#define W_  256
#define HW  (H_ * W_)
#define HW4 (HW / 4)               // float4 per (b,c) plane
#define KS  7
#define PADK 3
#define WPAD (W_ + 2 * PADK)       // 262

__device__ float g_avg[B_ * HW];
__device__ float g_max[B_ * HW];

__global__ __launch_bounds__(256) void reduce_kernel(const float4* __restrict__ x) {
    int g  = blockIdx.x * 256 + threadIdx.x;
    int b  = g >> 14;
    int hw = g & (HW4 - 1);

    const float4* p = x + ((size_t)b * C_) * HW4 + hw;

    float4 s = make_float4(0.f, 0.f, 0.f, 0.f);
    float4 m = make_float4(-FLT_MAX, -FLT_MAX, -FLT_MAX, -FLT_MAX);

    #pragma unroll 16
    for (int c = 0; c < C_; ++c) {
        float4 v = __ldcs(p + (size_t)c * HW4);
        s.x += v.x; s.y += v.y; s.z += v.z; s.w += v.w;
        m.x = fmaxf(m.x, v.x); m.y = fmaxf(m.y, v.y);
        m.z = fmaxf(m.z, v.z); m.w = fmaxf(m.w, v.w);
    }

    const float inv = 1.0f / (float)C_;
    float4 a = make_float4(s.x * inv, s.y * inv, s.z * inv, s.w * inv);
    reinterpret_cast<float4*>(g_avg)[g] = a;   // default policy: keep in L2
    reinterpret_cast<float4*>(g_max)[g] = m;
}

__global__ __launch_bounds__(256) void fuse_kernel(const float* __restrict__ x,
                                                   const float* __restrict__ conv_w,
                                                   const float* __restrict__ conv_b,
                                                   float* __restrict__ out) {
    __shared__ float sw[2 * KS * KS];                    // 98 weights
    __shared__ float sm[2 * KS * WPAD];                  // 7 halo rows x 2 ch, padded
    __shared__ __align__(16) float smask[W_];            // final mask for this row

    const int tid = threadIdx.x;
    const int b   = blockIdx.x >> 8;                     // blockIdx = b*H + h
    const int h   = blockIdx.x & (H_ - 1);

    if (tid < 2 * KS * KS) sw[tid] = __ldg(&conv_w[tid]);

    // Stage padded halo rows: sm[(ic*7+kh)*WPAD + (wc+3)], zeros in aprons/OOB rows.
    for (int i = tid; i < 2 * KS * WPAD; i += 256) {
        int ic = i / (KS * WPAD);
        int r  = i - ic * (KS * WPAD);
        int kh = r / WPAD;
        int wp = r - kh * WPAD;                          // 0..261
        int wc = wp - PADK;                              // -3..258
        int hh = h + kh - PADK;
        float v = 0.f;
        if (hh >= 0 && hh < H_ && wc >= 0 && wc < W_) {
            const float* plane = ic ? g_max : g_avg;
            v = __ldg(&plane[((size_t)b * H_ + hh) * W_ + wc]);  // L2 hit
        }
        sm[i] = v;
    }
    __syncthreads();

    // Branch-free conv for pixel w = tid; sigmoid -> smask.
    {
        float acc = __ldg(&conv_b[0]);
        #pragma unroll
        for (int ic = 0; ic < 2; ++ic) {
            #pragma unroll
            for (int kh = 0; kh < KS; ++kh) {
                const float* row = &sm[(ic * KS + kh) * WPAD + tid];
                const float* wr  = &sw[(ic * KS + kh) * KS];
                #pragma unroll
                for (int kw = 0; kw < KS; ++kw)
                    acc += row[kw] * wr[kw];
            }
        }
        smask[tid] = 1.0f / (1.0f + __expf(-acc));
    }
    __syncthreads();

    // Scale phase: 256 threads = 4 channels x 64 float4-columns per iteration.
    const int q    = tid & 63;                 // float4 column within row
    const int csub = tid >> 6;                 // channel sub-index 0..3
    const float4 mk = reinterpret_cast<const float4*>(smask)[q];

    const float4* x4 = reinterpret_cast<const float4*>(x);
    float4*       o4 = reinterpret_cast<float4*>(out);
    size_t base = (((size_t)b * C_) * H_ + h) * (W_ / 4) + q;

    #pragma unroll 4
    for (int cg = 0; cg < C_ / 4; ++cg) {
        int c = cg * 4 + csub;
        size_t idx = base + (size_t)c * HW4;
        float4 v = __ldcs(&x4[idx]);
        v.x *= mk.x; v.y *= mk.y; v.z *= mk.z; v.w *= mk.w;
        __stcs(&o4[idx], v);
    }
}

extern "C" void kernel_launch(void* const* d_in, const int* in_sizes, int n_in,
                              void* d_out, int out_size) {
    const float* x      = (const float*)d_in[0];
    const float* conv_w = (const float*)d_in[1];
    const float* conv_b = (const float*)d_in[2];
    float* out          = (float*)d_out;

    reduce_kernel<<<(B_ * HW4) / 256, 256>>>((const float4*)x);
    fuse_kernel<<<B_ * H_, 256>>>(x, conv_w, conv_b, out);
}